// round 1
// baseline (speedup 1.0000x reference)
#include <cuda_runtime.h>
#include <cuda_bf16.h>

// Chamfer distance: B=8, N=M=4096, D=3.
// dist(p,g) = |p|^2 + |g|^2 - 2 p.g ; min over other set both ways; mean+mean.
// Inner-loop trick: min_g |p-g|^2 = |p|^2 + min_g(|g|^2 - 2 p.g), clamp >= 0.

constexpr int B      = 8;
constexpr int NPTS   = 4096;
constexpr int THREADS = 512;
constexpr int CHUNKS = NPTS / THREADS;       // 8 chunks of points per (dir,batch)
constexpr int TILE   = 2048;                 // gt tile staged in shared (32KB as float4)
constexpr int NBLOCKS = 2 * B * CHUNKS;      // 128 blocks: dir in {0,1}

__device__ float g_partial[NBLOCKS];

__global__ __launch_bounds__(THREADS) void chamfer_min_kernel(
    const float* __restrict__ pred, const float* __restrict__ gt)
{
    __shared__ float4 s[TILE];

    const int bx    = blockIdx.x;
    const int dir   = bx >> 6;          // 0: pred->gt, 1: gt->pred
    const int rem   = bx & 63;
    const int b     = rem >> 3;
    const int chunk = rem & 7;

    const float* __restrict__ src = (dir == 0) ? pred : gt;
    const float* __restrict__ tgt = (dir == 0) ? gt   : pred;
    const float* sp = src + (size_t)b * NPTS * 3;
    const float* tp = tgt + (size_t)b * NPTS * 3;

    const int tid = threadIdx.x;
    const int pi  = chunk * THREADS + tid;

    const float px = sp[pi * 3 + 0];
    const float py = sp[pi * 3 + 1];
    const float pz = sp[pi * 3 + 2];
    const float mx = -2.0f * px, my = -2.0f * py, mz = -2.0f * pz;
    const float x2 = fmaf(px, px, fmaf(py, py, pz * pz));

    float b0 = 3.4e38f, b1 = 3.4e38f, b2 = 3.4e38f, b3 = 3.4e38f;

    for (int t = 0; t < NPTS; t += TILE) {
        // Stage TILE target points into shared as {x, y, z, |g|^2}
        for (int i = tid; i < TILE; i += THREADS) {
            const float* g = tp + (size_t)(t + i) * 3;
            const float gx = g[0], gy = g[1], gz = g[2];
            s[i] = make_float4(gx, gy, gz, fmaf(gx, gx, fmaf(gy, gy, gz * gz)));
        }
        __syncthreads();

        #pragma unroll 4
        for (int k = 0; k < TILE; k += 4) {
            const float4 g0 = s[k + 0];
            const float4 g1 = s[k + 1];
            const float4 g2 = s[k + 2];
            const float4 g3 = s[k + 3];
            const float d0 = fmaf(mx, g0.x, fmaf(my, g0.y, fmaf(mz, g0.z, g0.w)));
            const float d1 = fmaf(mx, g1.x, fmaf(my, g1.y, fmaf(mz, g1.z, g1.w)));
            const float d2 = fmaf(mx, g2.x, fmaf(my, g2.y, fmaf(mz, g2.z, g2.w)));
            const float d3 = fmaf(mx, g3.x, fmaf(my, g3.y, fmaf(mz, g3.z, g3.w)));
            b0 = fminf(b0, d0);
            b1 = fminf(b1, d1);
            b2 = fminf(b2, d2);
            b3 = fminf(b3, d3);
        }
        __syncthreads();
    }

    float res = fmaxf(x2 + fminf(fminf(b0, b1), fminf(b2, b3)), 0.0f);

    // Block reduction (deterministic): warp shuffle then cross-warp via shared
    #pragma unroll
    for (int off = 16; off; off >>= 1)
        res += __shfl_down_sync(0xffffffffu, res, off);

    __shared__ float wsum[16];
    const int wid = tid >> 5, lid = tid & 31;
    if (lid == 0) wsum[wid] = res;
    __syncthreads();
    if (wid == 0) {
        float v = (lid < 16) ? wsum[lid] : 0.0f;
        #pragma unroll
        for (int off = 8; off; off >>= 1)
            v += __shfl_down_sync(0xffffffffu, v, off);
        if (lid == 0) g_partial[bx] = v;
    }
}

__global__ void chamfer_finalize_kernel(float* __restrict__ out)
{
    __shared__ float s[NBLOCKS];
    const int tid = threadIdx.x;
    s[tid] = g_partial[tid];
    __syncthreads();
    if (tid == 0) {
        float s1 = 0.0f, s2 = 0.0f;
        #pragma unroll 8
        for (int i = 0; i < NBLOCKS / 2; ++i)        s1 += s[i];
        #pragma unroll 8
        for (int i = NBLOCKS / 2; i < NBLOCKS; ++i)  s2 += s[i];
        const float inv = 1.0f / (float)(B * NPTS);
        out[0] = s1 * inv + s2 * inv;
    }
}

extern "C" void kernel_launch(void* const* d_in, const int* in_sizes, int n_in,
                              void* d_out, int out_size)
{
    const float* pred = (const float*)d_in[0];
    const float* gt   = (const float*)d_in[1];
    float* out        = (float*)d_out;

    chamfer_min_kernel<<<NBLOCKS, THREADS>>>(pred, gt);
    chamfer_finalize_kernel<<<1, NBLOCKS>>>(out);
}

// round 2
// speedup vs baseline: 1.0514x; 1.0514x over previous
#include <cuda_runtime.h>
#include <cstdint>

// Chamfer distance: B=8, N=M=4096, D=3.
// min_g |p-g|^2 = |p|^2 + min_g(|g|^2 - 2 p.g), clamp >= 0 (clamp commutes with min).
// Inner loop: packed f32x2 FMAs, 2 target points per step:
//   7 instrs / 2 points = 2 LDS.128 + 3 FFMA2 + 2 FMNMX.

constexpr int B       = 8;
constexpr int NPTS    = 4096;
constexpr int THREADS = 512;
constexpr int CHUNKS  = NPTS / THREADS;       // 8 src chunks per (dir,batch)
constexpr int TILE    = 2048;                 // target points staged per tile (32KB)
constexpr int NBLOCKS = 2 * B * CHUNKS;       // 128

__device__ float        g_partial[NBLOCKS];
__device__ unsigned int g_count;              // zero-init; reset by elected block

__device__ __forceinline__ uint64_t pack2(float lo, float hi) {
    uint64_t r; asm("mov.b64 %0, {%1,%2};" : "=l"(r) : "f"(lo), "f"(hi)); return r;
}
__device__ __forceinline__ uint64_t fma2(uint64_t a, uint64_t b, uint64_t c) {
    uint64_t d; asm("fma.rn.f32x2 %0, %1, %2, %3;" : "=l"(d) : "l"(a), "l"(b), "l"(c)); return d;
}
__device__ __forceinline__ void unpack2(uint64_t v, float& lo, float& hi) {
    asm("mov.b64 {%0,%1}, %2;" : "=f"(lo), "=f"(hi) : "l"(v));
}

__global__ __launch_bounds__(THREADS) void chamfer_kernel(
    const float* __restrict__ pred, const float* __restrict__ gt,
    float* __restrict__ out)
{
    // Pair-interleaved target stage: for pair j,
    //   s[2j]   = {x0, x1, y0, y1}
    //   s[2j+1] = {z0, z1, w0, w1}   with w = |g|^2
    __shared__ float4 s[TILE];            // 2048 float4 = 32KB (16B per point)
    __shared__ float  wsum[16];
    __shared__ int    s_last;

    const int bx    = blockIdx.x;
    const int dir   = bx >> 6;            // 0: pred->gt, 1: gt->pred
    const int rem   = bx & 63;
    const int b     = rem >> 3;
    const int chunk = rem & 7;

    const float* __restrict__ src = (dir == 0) ? pred : gt;
    const float* __restrict__ tgt = (dir == 0) ? gt   : pred;
    const float* sp = src + (size_t)b * NPTS * 3;
    const float* tp = tgt + (size_t)b * NPTS * 3;

    const int tid = threadIdx.x;
    const int pi  = chunk * THREADS + tid;

    const float px = sp[pi * 3 + 0];
    const float py = sp[pi * 3 + 1];
    const float pz = sp[pi * 3 + 2];
    const float x2 = fmaf(px, px, fmaf(py, py, pz * pz));
    const uint64_t mx2 = pack2(-2.0f * px, -2.0f * px);
    const uint64_t my2 = pack2(-2.0f * py, -2.0f * py);
    const uint64_t mz2 = pack2(-2.0f * pz, -2.0f * pz);

    float b0 = 3.4e38f, b1 = 3.4e38f, b2 = 3.4e38f, b3 = 3.4e38f;

    const ulonglong2* s2 = reinterpret_cast<const ulonglong2*>(s);

    for (int t = 0; t < NPTS; t += TILE) {
        // Stage TILE target points as pairs (2 pairs per thread per tile).
        for (int j = tid; j < TILE / 2; j += THREADS) {
            const float2* g = reinterpret_cast<const float2*>(tp + (size_t)(t + 2 * j) * 3);
            const float2 a = g[0];    // x0, y0
            const float2 c = g[1];    // z0, x1
            const float2 e = g[2];    // y1, z1
            const float w0 = fmaf(a.x, a.x, fmaf(a.y, a.y, c.x * c.x));
            const float w1 = fmaf(c.y, c.y, fmaf(e.x, e.x, e.y * e.y));
            s[2 * j + 0] = make_float4(a.x, c.y, a.y, e.x);   // x0,x1,y0,y1
            s[2 * j + 1] = make_float4(c.x, e.y, w0,  w1);    // z0,z1,w0,w1
        }
        __syncthreads();

        #pragma unroll 4
        for (int j = 0; j < TILE / 2; j += 2) {
            const ulonglong2 P0 = s2[2 * j + 0];   // xx01, yy01
            const ulonglong2 Q0 = s2[2 * j + 1];   // zz01, ww01
            const ulonglong2 P1 = s2[2 * j + 2];
            const ulonglong2 Q1 = s2[2 * j + 3];

            uint64_t t0 = fma2(mz2, Q0.x, Q0.y);
            uint64_t t1 = fma2(mz2, Q1.x, Q1.y);
            t0 = fma2(my2, P0.y, t0);
            t1 = fma2(my2, P1.y, t1);
            t0 = fma2(mx2, P0.x, t0);
            t1 = fma2(mx2, P1.x, t1);

            float d0, d1, d2, d3;
            unpack2(t0, d0, d1);
            unpack2(t1, d2, d3);
            b0 = fminf(b0, d0);
            b1 = fminf(b1, d1);
            b2 = fminf(b2, d2);
            b3 = fminf(b3, d3);
        }
        __syncthreads();
    }

    float res = fmaxf(x2 + fminf(fminf(b0, b1), fminf(b2, b3)), 0.0f);

    // Block reduction (fixed order -> deterministic)
    #pragma unroll
    for (int off = 16; off; off >>= 1)
        res += __shfl_down_sync(0xffffffffu, res, off);

    const int wid = tid >> 5, lid = tid & 31;
    if (lid == 0) wsum[wid] = res;
    __syncthreads();
    if (wid == 0) {
        float v = (lid < 16) ? wsum[lid] : 0.0f;
        #pragma unroll
        for (int off = 8; off; off >>= 1)
            v += __shfl_down_sync(0xffffffffu, v, off);
        if (lid == 0) g_partial[bx] = v;
    }

    // Last-block election; elected block performs the (deterministic) final sum.
    if (tid == 0) {
        __threadfence();
        const unsigned int old = atomicAdd(&g_count, 1u);
        s_last = (old == (unsigned int)(NBLOCKS - 1)) ? 1 : 0;
    }
    __syncthreads();

    if (s_last) {
        float v = (tid < NBLOCKS) ? ((volatile float*)g_partial)[tid] : 0.0f;
        #pragma unroll
        for (int off = 16; off; off >>= 1)
            v += __shfl_down_sync(0xffffffffu, v, off);
        if (lid == 0) wsum[wid] = v;
        __syncthreads();
        if (wid == 0) {
            float t = (lid < 16) ? wsum[lid] : 0.0f;
            #pragma unroll
            for (int off = 8; off; off >>= 1)
                t += __shfl_down_sync(0xffffffffu, t, off);
            if (lid == 0) {
                out[0] = t * (1.0f / (float)(B * NPTS));
                g_count = 0;   // reset for next graph replay
            }
        }
    }
}

extern "C" void kernel_launch(void* const* d_in, const int* in_sizes, int n_in,
                              void* d_out, int out_size)
{
    const float* pred = (const float*)d_in[0];
    const float* gt   = (const float*)d_in[1];
    float* out        = (float*)d_out;

    chamfer_kernel<<<NBLOCKS, THREADS>>>(pred, gt, out);
}

// round 3
// speedup vs baseline: 1.7179x; 1.6340x over previous
#include <cuda_runtime.h>
#include <cstdint>

// Chamfer distance: B=8, N=M=4096, D=3.
// min_g |p-g|^2 = |p|^2 + min_g(|g|^2 - 2 p.g), clamp >= 0.
// Register-tiled: each thread holds R=4 src points; targets split 4-way across
// blocks; per-src partial mins combined by a small finalize kernel.

constexpr int B       = 8;
constexpr int NPTS    = 4096;
constexpr int THREADS = 512;
constexpr int R       = 4;                  // src points per thread
constexpr int TSPLIT  = 4;                  // target splits per (dir,b)
constexpr int TTARG   = NPTS / TSPLIT;      // 1024 targets staged per block
constexpr int SRC_PER_BLOCK = THREADS * R;  // 2048
constexpr int SCHUNKS = NPTS / SRC_PER_BLOCK; // 2
constexpr int NBLOCKS = 2 * B * SCHUNKS * TSPLIT; // 128

constexpr int FBLOCKS  = 64;
constexpr int FTHREADS = 256;

__device__ float        g_pmin[2 * B * NPTS * TSPLIT]; // [dir][b][src][tsp]
__device__ float        g_fpartial[FBLOCKS];
__device__ unsigned int g_count;            // zero-init; reset by elected block

__device__ __forceinline__ uint64_t pack2(float lo, float hi) {
    uint64_t r; asm("mov.b64 %0, {%1,%2};" : "=l"(r) : "f"(lo), "f"(hi)); return r;
}
__device__ __forceinline__ uint64_t fma2(uint64_t a, uint64_t b, uint64_t c) {
    uint64_t d; asm("fma.rn.f32x2 %0, %1, %2, %3;" : "=l"(d) : "l"(a), "l"(b), "l"(c)); return d;
}
__device__ __forceinline__ void unpack2(uint64_t v, float& lo, float& hi) {
    asm("mov.b64 {%0,%1}, %2;" : "=f"(lo), "=f"(hi) : "l"(v));
}

__global__ __launch_bounds__(THREADS) void chamfer_main(
    const float* __restrict__ pred, const float* __restrict__ gt)
{
    // Pair-interleaved stage: pair j -> s[2j]={x0,x1,y0,y1}, s[2j+1]={z0,z1,w0,w1}
    __shared__ float4 s[TTARG];             // 1024 float4 = 16KB

    const int bx    = blockIdx.x;
    const int tsp   = bx & 3;
    const int chunk = (bx >> 2) & 1;
    const int b     = (bx >> 3) & 7;
    const int dir   = bx >> 6;

    const float* __restrict__ src = (dir == 0) ? pred : gt;
    const float* __restrict__ tgt = (dir == 0) ? gt   : pred;
    const float* sp = src + (size_t)b * NPTS * 3;
    const float* tp = tgt + ((size_t)b * NPTS + (size_t)tsp * TTARG) * 3;

    const int tid = threadIdx.x;

    // Stage: 512 pairs, one per thread.
    {
        const int j = tid;
        const float2* g = reinterpret_cast<const float2*>(tp + 6 * j);
        const float2 a = g[0];   // x0, y0
        const float2 c = g[1];   // z0, x1
        const float2 e = g[2];   // y1, z1
        const float w0 = fmaf(a.x, a.x, fmaf(a.y, a.y, c.x * c.x));
        const float w1 = fmaf(c.y, c.y, fmaf(e.x, e.x, e.y * e.y));
        s[2 * j + 0] = make_float4(a.x, c.y, a.y, e.x);
        s[2 * j + 1] = make_float4(c.x, e.y, w0,  w1);
    }

    // Load R src points (stride-THREADS for coalescing across the block).
    const int s0 = chunk * SRC_PER_BLOCK + tid;
    uint64_t mx[R], my[R], mz[R];
    float x2[R], bmin[R];
    #pragma unroll
    for (int k = 0; k < R; ++k) {
        const float* p = sp + (size_t)(s0 + k * THREADS) * 3;
        const float px = p[0], py = p[1], pz = p[2];
        x2[k] = fmaf(px, px, fmaf(py, py, pz * pz));
        mx[k] = pack2(-2.0f * px, -2.0f * px);
        my[k] = pack2(-2.0f * py, -2.0f * py);
        mz[k] = pack2(-2.0f * pz, -2.0f * pz);
        bmin[k] = 3.4e38f;
    }
    __syncthreads();

    const ulonglong2* s2 = reinterpret_cast<const ulonglong2*>(s);

    #pragma unroll 4
    for (int j = 0; j < TTARG / 2; j += 2) {
        const ulonglong2 P0 = s2[2 * j + 0];  // xx01, yy01
        const ulonglong2 Q0 = s2[2 * j + 1];  // zz01, ww01
        const ulonglong2 P1 = s2[2 * j + 2];
        const ulonglong2 Q1 = s2[2 * j + 3];

        #pragma unroll
        for (int k = 0; k < R; ++k) {
            uint64_t t0 = fma2(mz[k], Q0.x, Q0.y);
            uint64_t t1 = fma2(mz[k], Q1.x, Q1.y);
            t0 = fma2(my[k], P0.y, t0);
            t1 = fma2(my[k], P1.y, t1);
            t0 = fma2(mx[k], P0.x, t0);
            t1 = fma2(mx[k], P1.x, t1);
            float d0, d1, d2, d3;
            unpack2(t0, d0, d1);
            unpack2(t1, d2, d3);
            bmin[k] = fminf(bmin[k], fminf(fminf(d0, d1), fminf(d2, d3)));
        }
    }

    // Partial result per src point (unclamped): x2 + min over this target slice.
    const int pbase = ((dir * B + b) * NPTS + s0) * TSPLIT + tsp;
    #pragma unroll
    for (int k = 0; k < R; ++k)
        g_pmin[pbase + k * THREADS * TSPLIT] = x2[k] + bmin[k];
}

__global__ __launch_bounds__(FTHREADS) void chamfer_finalize(float* __restrict__ out)
{
    __shared__ float wsum[FTHREADS / 32];
    __shared__ int   s_last;

    const int tid = threadIdx.x;
    const int bx  = blockIdx.x;
    const int wid = tid >> 5, lid = tid & 31;

    float sum = 0.0f;
    #pragma unroll
    for (int k = 0; k < 4; ++k) {
        const int sidx = bx * (4 * FTHREADS) + k * FTHREADS + tid;
        const float4 v = reinterpret_cast<const float4*>(g_pmin)[sidx];
        sum += fmaxf(fminf(fminf(v.x, v.y), fminf(v.z, v.w)), 0.0f);
    }

    #pragma unroll
    for (int off = 16; off; off >>= 1)
        sum += __shfl_down_sync(0xffffffffu, sum, off);
    if (lid == 0) wsum[wid] = sum;
    __syncthreads();
    if (wid == 0) {
        float v = (lid < FTHREADS / 32) ? wsum[lid] : 0.0f;
        #pragma unroll
        for (int off = 4; off; off >>= 1)
            v += __shfl_down_sync(0xffffffffu, v, off);
        if (lid == 0) g_fpartial[bx] = v;
    }

    if (tid == 0) {
        __threadfence();
        const unsigned int old = atomicAdd(&g_count, 1u);
        s_last = (old == (unsigned int)(FBLOCKS - 1)) ? 1 : 0;
    }
    __syncthreads();

    if (s_last) {
        float v = (tid < FBLOCKS) ? ((volatile float*)g_fpartial)[tid] : 0.0f;
        #pragma unroll
        for (int off = 16; off; off >>= 1)
            v += __shfl_down_sync(0xffffffffu, v, off);
        if (lid == 0) wsum[wid] = v;
        __syncthreads();
        if (wid == 0) {
            float t = (lid < FTHREADS / 32) ? wsum[lid] : 0.0f;
            #pragma unroll
            for (int off = 4; off; off >>= 1)
                t += __shfl_down_sync(0xffffffffu, t, off);
            if (lid == 0) {
                out[0] = t * (1.0f / (float)(B * NPTS));
                g_count = 0;  // reset for next graph replay
            }
        }
    }
}

extern "C" void kernel_launch(void* const* d_in, const int* in_sizes, int n_in,
                              void* d_out, int out_size)
{
    const float* pred = (const float*)d_in[0];
    const float* gt   = (const float*)d_in[1];
    float* out        = (float*)d_out;

    chamfer_main<<<NBLOCKS, THREADS>>>(pred, gt);
    chamfer_finalize<<<FBLOCKS, FTHREADS>>>(out);
}